// round 10
// baseline (speedup 1.0000x reference)
#include <cuda_runtime.h>
#include <cstdint>
#include <cstddef>

#define S_LEN 2048
#define B_DIM 64
#define I_DIM 512
#define H_DIM 512
#define G_DIM 2048  // 4*H

// ---------------- scratch (static device globals) -------------------------------
__device__ __align__(16) float g_xw[(size_t)S_LEN * B_DIM * G_DIM];   // 1 GB
__device__ __align__(16) float g_h[2][B_DIM * H_DIM];
__device__ __align__(16) unsigned long long g_flags[128 * 16];  // 128B-strided flags

// ---------------- packed f32x2 helpers ------------------------------------------
__device__ __forceinline__ unsigned long long pk2(float lo, float hi) {
    unsigned long long r;
    asm("mov.b64 %0, {%1, %2};" : "=l"(r) : "f"(lo), "f"(hi));
    return r;
}
__device__ __forceinline__ void upk2(unsigned long long v, float& lo, float& hi) {
    asm("mov.b64 {%0, %1}, %2;" : "=f"(lo), "=f"(hi) : "l"(v));
}
__device__ __forceinline__ void ffma2(unsigned long long& d, unsigned long long a, unsigned long long b) {
    asm("fma.rn.f32x2 %0, %1, %2, %0;" : "+l"(d) : "l"(a), "l"(b));
}
__device__ __forceinline__ unsigned long long addf2(unsigned long long a, unsigned long long b) {
    unsigned long long r;
    asm("add.rn.f32x2 %0, %1, %2;" : "=l"(r) : "l"(a), "l"(b));
    return r;
}
// MUFU-based activations (abs err ~1e-6, far inside 1e-3 budget)
__device__ __forceinline__ float sigmoid_f(float x) {
    return __fdividef(1.0f, 1.0f + __expf(-x));
}
__device__ __forceinline__ float tanh_f(float x) {
    float e = __expf(2.0f * x);
    return 1.0f - __fdividef(2.0f, e + 1.0f);
}
// ---------------- release/acquire flag ops --------------------------------------
__device__ __forceinline__ void st_release_gpu(unsigned long long* p, unsigned long long v) {
    asm volatile("st.release.gpu.u64 [%0], %1;" :: "l"(p), "l"(v) : "memory");
}
__device__ __forceinline__ unsigned long long ld_acquire_gpu(const unsigned long long* p) {
    unsigned long long v;
    asm volatile("ld.acquire.gpu.u64 %0, [%1];" : "=l"(v) : "l"(p) : "memory");
    return v;
}
__device__ __forceinline__ void wait_flag_ge(const unsigned long long* f, unsigned long long tgt) {
    int spins = 0;
    while (ld_acquire_gpu(f) < tgt) {
        if (++spins > 32) { __nanosleep(64); spins = 16; }
    }
}

// =====================================================================
// Kernel 1: xW = x @ W + bias (unchanged — at its f32x2 issue floor)
// =====================================================================
__global__ __launch_bounds__(256, 2) void gemm_xw_kernel(
    const float* __restrict__ x, const float* __restrict__ W,
    const float* __restrict__ bias)
{
    __shared__ float As[8][128];
    __shared__ float Bs[8][128];

    const int t  = threadIdx.x;
    const int m0 = blockIdx.y * 128;
    const int n0 = blockIdx.x * 128;
    const int tx = t & 15;
    const int ty = t >> 4;

    const int arow = t >> 1, akc = (t & 1) * 4;
    const int brow = t >> 5, bnc = (t & 31) * 4;

    unsigned long long acc[8][4];
    #pragma unroll
    for (int m = 0; m < 8; m++)
        #pragma unroll
        for (int n = 0; n < 4; n++) acc[m][n] = 0ULL;

    float4 av = *(const float4*)(x + (size_t)(m0 + arow) * I_DIM + akc);
    float4 bv = *(const float4*)(W + (size_t)brow * G_DIM + n0 + bnc);

    for (int kt = 0; kt < 64; kt++) {
        __syncthreads();
        As[akc + 0][arow] = av.x;
        As[akc + 1][arow] = av.y;
        As[akc + 2][arow] = av.z;
        As[akc + 3][arow] = av.w;
        *(float4*)&Bs[brow][bnc] = bv;
        __syncthreads();
        if (kt < 63) {
            av = *(const float4*)(x + (size_t)(m0 + arow) * I_DIM + (kt + 1) * 8 + akc);
            bv = *(const float4*)(W + (size_t)((kt + 1) * 8 + brow) * G_DIM + n0 + bnc);
        }
        #pragma unroll
        for (int kk = 0; kk < 8; kk++) {
            float4 a01 = *(const float4*)&As[kk][ty * 8];
            float4 a23 = *(const float4*)&As[kk][ty * 8 + 4];
            ulonglong2 b01 = *(const ulonglong2*)&Bs[kk][tx * 8];
            ulonglong2 b23 = *(const ulonglong2*)&Bs[kk][tx * 8 + 4];
            float am[8] = {a01.x, a01.y, a01.z, a01.w, a23.x, a23.y, a23.z, a23.w};
            #pragma unroll
            for (int m = 0; m < 8; m++) {
                unsigned long long aa = pk2(am[m], am[m]);
                ffma2(acc[m][0], aa, b01.x);
                ffma2(acc[m][1], aa, b01.y);
                ffma2(acc[m][2], aa, b23.x);
                ffma2(acc[m][3], aa, b23.y);
            }
        }
    }

    float bb[8];
    #pragma unroll
    for (int i = 0; i < 8; i++) bb[i] = bias[n0 + tx * 8 + i];
    #pragma unroll
    for (int m = 0; m < 8; m++) {
        float c[8];
        upk2(acc[m][0], c[0], c[1]);
        upk2(acc[m][1], c[2], c[3]);
        upk2(acc[m][2], c[4], c[5]);
        upk2(acc[m][3], c[6], c[7]);
        #pragma unroll
        for (int i = 0; i < 8; i++) c[i] += bb[i];
        float* op = g_xw + (size_t)(m0 + ty * 8 + m) * G_DIM + n0 + tx * 8;
        __stcs((float4*)op,       make_float4(c[0], c[1], c[2], c[3]));
        __stcs((float4*)(op + 4), make_float4(c[4], c[5], c[6], c[7]));
    }
}

// =====================================================================
// Kernel 2: persistent recurrence. 256 thr/CTA, grid (64,2) = 128 CTAs,
// two independent 64-CTA barrier domains.
// CTA (j,bq): batches [bq*32,+32), CTA cols c in [0,32):
//   global gate col gc = (c>>3)*512 + j*8 + (c&7).
// FMA phase: thread = (k-quarter q4 = t>>6) x (tile = t&63: cg=tile&7 ->
//   cols cg*4..+3, bg=tile>>3 -> batches bg*4..+3). 4x4 f32x2 accs over 32 kq.
//   Delivered smem bytes: 128B/thread/kq -> 1MB/step (vs 1.57MB in R4).
// Reduction: partials -> smem (reusing dead h_s region) -> 1 cell/thread
//   eltwise (b=t>>3, hc=t&7), same as R9.
// U_s[kq][32 c][4 k] pitch 128 fl; h_s[b][512 k] pitch 520 fl (bank-spread).
// =====================================================================
#define NQ       128
#define UPITCH   128
#define KPITCH   520
#define REDPITCH 257   // ull per slot-row (pad -> <=2-way read conflicts)
#define SMEM_FLOATS (NQ * UPITCH + 32 * KPITCH)
#define SMEM_BYTES  (SMEM_FLOATS * 4)

__global__ __launch_bounds__(256, 1) void lstm_rec_kernel(
    const float* __restrict__ U, float* __restrict__ out, size_t out_size)
{
    extern __shared__ float sm[];
    float* U_s = sm;                      // [128][128]
    float* h_s = sm + NQ * UPITCH;        // [32][520]; reused as red buffer

    const int t   = threadIdx.x;          // 0..255
    const int j   = blockIdx.x;           // 0..63
    const int bq  = blockIdx.y;           // 0..1  (barrier domain)

    // FMA-phase mapping
    const int q4 = t >> 6;                // k quarter 0..3
    const int cg = t & 7;                 // col group: cols cg*4..+3
    const int bg = (t >> 3) & 7;          // batch group: b bg*4..+3

    // eltwise-phase mapping (fixed per thread across steps -> c_reg)
    const int hc = t & 7;
    const int b  = t >> 3;                // 0..31
    const int col = j * 8 + hc;
    const int gb  = bq * 32 + b;

    unsigned long long* dom_flags = g_flags + (size_t)bq * 64 * 16;
    unsigned long long* red = (unsigned long long*)h_s;   // [16][257] overlay

    // ---- U slice load: U_s[kq][c][ki] <- U[k][(c>>3)*512 + j*8 + (c&7)]
    for (int idx = t; idx < 512 * 32; idx += 256) {
        int k = idx >> 5;
        int c = idx & 31;
        float v = U[(size_t)k * G_DIM + (c >> 3) * H_DIM + j * 8 + (c & 7)];
        U_s[(k >> 2) * UPITCH + c * 4 + (k & 3)] = v;
    }

    // ---- zero h_buf[0] (domain half: 64 CTAs x 256 floats = 32x512)
    {
        float* hz = g_h[0] + (size_t)bq * 32 * H_DIM;
        hz[j * 256 + t] = 0.0f;
    }

    unsigned long long base = ld_acquire_gpu(&dom_flags[j * 16]);

    // init barrier (domain-local)
    __syncthreads();
    if (t == 0) st_release_gpu(&dom_flags[j * 16], base + 1);
    if (t < 64) wait_flag_ge(&dom_flags[t * 16], base + 1);
    __syncthreads();

    float c_reg = 0.0f;

    for (int ts = 0; ts < S_LEN; ts++) {
        const int cur = ts & 1, nxt = cur ^ 1;

        // ---- xW prefetch for owned cell's 4 gates (hides DRAM latency)
        float xw[4];
        {
            const float* xb = g_xw + ((size_t)ts * B_DIM + gb) * G_DIM + j * 8 + hc;
            #pragma unroll
            for (int q = 0; q < 4; q++) xw[q] = __ldcs(xb + q * H_DIM);
        }

        // ---- wait for previous step's h (domain-local)
        if (ts > 0) {
            unsigned long long tgt = base + 1 + (unsigned long long)ts;
            if (t < 64) wait_flag_ge(&dom_flags[t * 16], tgt);
            __syncthreads();
        }

        // ---- h tile load: 32 rows x 512 floats; STS contiguous, coalesced
        {
            const float* hb = g_h[cur] + (size_t)bq * 32 * H_DIM;
            #pragma unroll
            for (int n = 0; n < 16; n++) {
                int idx = n * 256 + t;        // 0..4095
                int row = idx >> 7;           // 0..31
                int c4  = idx & 127;          // float4 index in row
                float4 v = __ldcg((const float4*)(hb + row * H_DIM + c4 * 4));
                *(float4*)&h_s[row * KPITCH + c4 * 4] = v;
            }
        }
        __syncthreads();

        // ---- FMA: 4 cols x 4 batches x 32 kq per thread (k-quarter q4)
        unsigned long long acc[4][4];   // [ci][bi], f32x2 over (k even, k odd)
        #pragma unroll
        for (int ci = 0; ci < 4; ci++)
            #pragma unroll
            for (int bi = 0; bi < 4; bi++) acc[ci][bi] = 0ULL;

        const char* up = (const char*)(U_s + q4 * 32 * UPITCH + cg * 16);
        const char* hp = (const char*)(h_s + bg * 4 * KPITCH) + q4 * 512;
        #pragma unroll 4
        for (int kq = 0; kq < 32; kq++) {
            ulonglong2 u0 = *(const ulonglong2*)(up);
            ulonglong2 u1 = *(const ulonglong2*)(up + 16);
            ulonglong2 u2 = *(const ulonglong2*)(up + 32);
            ulonglong2 u3 = *(const ulonglong2*)(up + 48);
            ulonglong2 h0 = *(const ulonglong2*)(hp);
            ulonglong2 h1 = *(const ulonglong2*)(hp + KPITCH * 4);
            ulonglong2 h2 = *(const ulonglong2*)(hp + KPITCH * 8);
            ulonglong2 h3 = *(const ulonglong2*)(hp + KPITCH * 12);
            ffma2(acc[0][0], h0.x, u0.x); ffma2(acc[0][0], h0.y, u0.y);
            ffma2(acc[0][1], h1.x, u0.x); ffma2(acc[0][1], h1.y, u0.y);
            ffma2(acc[0][2], h2.x, u0.x); ffma2(acc[0][2], h2.y, u0.y);
            ffma2(acc[0][3], h3.x, u0.x); ffma2(acc[0][3], h3.y, u0.y);
            ffma2(acc[1][0], h0.x, u1.x); ffma2(acc[1][0], h0.y, u1.y);
            ffma2(acc[1][1], h1.x, u1.x); ffma2(acc[1][1], h1.y, u1.y);
            ffma2(acc[1][2], h2.x, u1.x); ffma2(acc[1][2], h2.y, u1.y);
            ffma2(acc[1][3], h3.x, u1.x); ffma2(acc[1][3], h3.y, u1.y);
            ffma2(acc[2][0], h0.x, u2.x); ffma2(acc[2][0], h0.y, u2.y);
            ffma2(acc[2][1], h1.x, u2.x); ffma2(acc[2][1], h1.y, u2.y);
            ffma2(acc[2][2], h2.x, u2.x); ffma2(acc[2][2], h2.y, u2.y);
            ffma2(acc[2][3], h3.x, u2.x); ffma2(acc[2][3], h3.y, u2.y);
            ffma2(acc[3][0], h0.x, u3.x); ffma2(acc[3][0], h0.y, u3.y);
            ffma2(acc[3][1], h1.x, u3.x); ffma2(acc[3][1], h1.y, u3.y);
            ffma2(acc[3][2], h2.x, u3.x); ffma2(acc[3][2], h2.y, u3.y);
            ffma2(acc[3][3], h3.x, u3.x); ffma2(acc[3][3], h3.y, u3.y);
            up += UPITCH * 4;
            hp += 16;
        }

        // ---- all threads done reading h_s; reuse it as reduction buffer
        __syncthreads();
        {
            const int w = t;   // writer id = q4*64 + bg*8 + cg == t
            #pragma unroll
            for (int ci = 0; ci < 4; ci++)
                #pragma unroll
                for (int bi = 0; bi < 4; bi++)
                    red[(ci * 4 + bi) * REDPITCH + w] = acc[ci][bi];
        }
        __syncthreads();

        // ---- reduce 4 k-partials for owned cell (b, hc), all 4 gates
        float s[4];
        {
            const int slot = (hc & 3) * 4 + (b & 3);
            #pragma unroll
            for (int q = 0; q < 4; q++) {
                int c = q * 8 + hc;
                int tile = (b >> 2) * 8 + (c >> 2);
                unsigned long long v = red[slot * REDPITCH + tile];
                v = addf2(v, red[slot * REDPITCH +  64 + tile]);
                v = addf2(v, red[slot * REDPITCH + 128 + tile]);
                v = addf2(v, red[slot * REDPITCH + 192 + tile]);
                float l, h_;
                upk2(v, l, h_);
                s[q] = l + h_ + xw[q];
            }
        }

        float iv = sigmoid_f(s[0]);
        float fv = sigmoid_f(s[1]);
        float gv = tanh_f(s[2]);
        float ov = sigmoid_f(s[3]);

        c_reg = fv * c_reg + iv * gv;
        float hval = ov * tanh_f(c_reg);

        // ---- h store (critical), release, then out store (off-path)
        __stcg(&g_h[nxt][gb * H_DIM + col], hval);
        __syncthreads();
        if (ts < S_LEN - 1 && t == 0)
            st_release_gpu(&dom_flags[j * 16], base + 2 + (unsigned long long)ts);

        __stcs(&out[(size_t)ts * (B_DIM * H_DIM) + gb * H_DIM + col], hval);

        if (ts == S_LEN - 1) {
            const size_t SEQ  = (size_t)S_LEN * B_DIM * H_DIM;
            const size_t need = SEQ + 2 * (size_t)B_DIM * H_DIM;
            if (out_size >= need) {
                out[SEQ + gb * H_DIM + col]                         = hval;
                out[SEQ + (size_t)B_DIM * H_DIM + gb * H_DIM + col] = c_reg;
            }
        }
    }
}

// =====================================================================
extern "C" void kernel_launch(void* const* d_in, const int* in_sizes, int n_in,
                              void* d_out, int out_size) {
    const float* x    = (const float*)d_in[0];
    const float* W    = (const float*)d_in[1];
    const float* U    = (const float*)d_in[2];
    const float* bias = (const float*)d_in[3];
    float* out = (float*)d_out;
    (void)in_sizes; (void)n_in;

    cudaFuncSetAttribute(lstm_rec_kernel,
                         cudaFuncAttributeMaxDynamicSharedMemorySize, SMEM_BYTES);

    dim3 ggrid(G_DIM / 128, (S_LEN * B_DIM) / 128);  // (16, 1024)
    gemm_xw_kernel<<<ggrid, 256>>>(x, W, bias);

    dim3 rgrid(64, 2);  // 128 CTAs, 1/SM (smem-limited) -> all co-resident
    lstm_rec_kernel<<<rgrid, 256, SMEM_BYTES>>>(U, out, (size_t)out_size);
}

// round 11
// speedup vs baseline: 1.7140x; 1.7140x over previous
#include <cuda_runtime.h>
#include <cstdint>
#include <cstddef>

#define S_LEN 2048
#define B_DIM 64
#define I_DIM 512
#define H_DIM 512
#define G_DIM 2048  // 4*H

// ---------------- scratch (static device globals) -------------------------------
__device__ __align__(16) float g_xw[(size_t)S_LEN * B_DIM * G_DIM];   // 1 GB
__device__ __align__(16) float g_h[2][B_DIM * H_DIM];
__device__ __align__(16) unsigned long long g_flags[128 * 16];  // 128B-strided flags

// ---------------- packed f32x2 helpers ------------------------------------------
__device__ __forceinline__ unsigned long long pk2(float lo, float hi) {
    unsigned long long r;
    asm("mov.b64 %0, {%1, %2};" : "=l"(r) : "f"(lo), "f"(hi));
    return r;
}
__device__ __forceinline__ void upk2(unsigned long long v, float& lo, float& hi) {
    asm("mov.b64 {%0, %1}, %2;" : "=f"(lo), "=f"(hi) : "l"(v));
}
__device__ __forceinline__ void ffma2(unsigned long long& d, unsigned long long a, unsigned long long b) {
    asm("fma.rn.f32x2 %0, %1, %2, %0;" : "+l"(d) : "l"(a), "l"(b));
}
__device__ __forceinline__ unsigned long long addf2(unsigned long long a, unsigned long long b) {
    unsigned long long r;
    asm("add.rn.f32x2 %0, %1, %2;" : "=l"(r) : "l"(a), "l"(b));
    return r;
}
// MUFU-based activations (abs err ~1e-6, far inside 1e-3 budget)
__device__ __forceinline__ float sigmoid_f(float x) {
    return __fdividef(1.0f, 1.0f + __expf(-x));
}
__device__ __forceinline__ float tanh_f(float x) {
    float e = __expf(2.0f * x);
    return 1.0f - __fdividef(2.0f, e + 1.0f);
}
// ---------------- release/acquire flag ops --------------------------------------
__device__ __forceinline__ void st_release_gpu(unsigned long long* p, unsigned long long v) {
    asm volatile("st.release.gpu.u64 [%0], %1;" :: "l"(p), "l"(v) : "memory");
}
__device__ __forceinline__ unsigned long long ld_acquire_gpu(const unsigned long long* p) {
    unsigned long long v;
    asm volatile("ld.acquire.gpu.u64 %0, [%1];" : "=l"(v) : "l"(p) : "memory");
    return v;
}
__device__ __forceinline__ void wait_flag_ge(const unsigned long long* f, unsigned long long tgt) {
    int spins = 0;
    while (ld_acquire_gpu(f) < tgt) {
        if (++spins > 32) { __nanosleep(64); spins = 16; }
    }
}

// =====================================================================
// Kernel 1: xW = x @ W + bias (unchanged — at its f32x2 issue floor)
// =====================================================================
__global__ __launch_bounds__(256, 2) void gemm_xw_kernel(
    const float* __restrict__ x, const float* __restrict__ W,
    const float* __restrict__ bias)
{
    __shared__ float As[8][128];
    __shared__ float Bs[8][128];

    const int t  = threadIdx.x;
    const int m0 = blockIdx.y * 128;
    const int n0 = blockIdx.x * 128;
    const int tx = t & 15;
    const int ty = t >> 4;

    const int arow = t >> 1, akc = (t & 1) * 4;
    const int brow = t >> 5, bnc = (t & 31) * 4;

    unsigned long long acc[8][4];
    #pragma unroll
    for (int m = 0; m < 8; m++)
        #pragma unroll
        for (int n = 0; n < 4; n++) acc[m][n] = 0ULL;

    float4 av = *(const float4*)(x + (size_t)(m0 + arow) * I_DIM + akc);
    float4 bv = *(const float4*)(W + (size_t)brow * G_DIM + n0 + bnc);

    for (int kt = 0; kt < 64; kt++) {
        __syncthreads();
        As[akc + 0][arow] = av.x;
        As[akc + 1][arow] = av.y;
        As[akc + 2][arow] = av.z;
        As[akc + 3][arow] = av.w;
        *(float4*)&Bs[brow][bnc] = bv;
        __syncthreads();
        if (kt < 63) {
            av = *(const float4*)(x + (size_t)(m0 + arow) * I_DIM + (kt + 1) * 8 + akc);
            bv = *(const float4*)(W + (size_t)((kt + 1) * 8 + brow) * G_DIM + n0 + bnc);
        }
        #pragma unroll
        for (int kk = 0; kk < 8; kk++) {
            float4 a01 = *(const float4*)&As[kk][ty * 8];
            float4 a23 = *(const float4*)&As[kk][ty * 8 + 4];
            ulonglong2 b01 = *(const ulonglong2*)&Bs[kk][tx * 8];
            ulonglong2 b23 = *(const ulonglong2*)&Bs[kk][tx * 8 + 4];
            float am[8] = {a01.x, a01.y, a01.z, a01.w, a23.x, a23.y, a23.z, a23.w};
            #pragma unroll
            for (int m = 0; m < 8; m++) {
                unsigned long long aa = pk2(am[m], am[m]);
                ffma2(acc[m][0], aa, b01.x);
                ffma2(acc[m][1], aa, b01.y);
                ffma2(acc[m][2], aa, b23.x);
                ffma2(acc[m][3], aa, b23.y);
            }
        }
    }

    float bb[8];
    #pragma unroll
    for (int i = 0; i < 8; i++) bb[i] = bias[n0 + tx * 8 + i];
    #pragma unroll
    for (int m = 0; m < 8; m++) {
        float c[8];
        upk2(acc[m][0], c[0], c[1]);
        upk2(acc[m][1], c[2], c[3]);
        upk2(acc[m][2], c[4], c[5]);
        upk2(acc[m][3], c[6], c[7]);
        #pragma unroll
        for (int i = 0; i < 8; i++) c[i] += bb[i];
        float* op = g_xw + (size_t)(m0 + ty * 8 + m) * G_DIM + n0 + tx * 8;
        __stcs((float4*)op,       make_float4(c[0], c[1], c[2], c[3]));
        __stcs((float4*)(op + 4), make_float4(c[4], c[5], c[6], c[7]));
    }
}

// =====================================================================
// Kernel 2: persistent recurrence (R10 structure, conflict-free layouts).
// 256 thr/CTA, grid (64,2) = 128 CTAs, two 64-CTA barrier domains.
// FMA phase: thread = (q4 = t>>6 k-quarter) x (cg = t&7 -> cols cg*4..+3,
//   bg = (t>>3)&7... within-warp bg spans 4) 4x4 f32x2 accs over 32 kq.
// U layout: per kq, col-group cg at skewed offset cg*20 floats (kq pitch 160)
//   -> lane stride 20 mod 32 hits 8 distinct bank groups (0 conflicts).
// h layout: row b at b*512 + (b>>2)*8 floats
//   -> bg lane stride 2056 mod 32 = 8: 4 distinct bank groups (0 conflicts).
// Reduction partials overlay the h region ([16][257] ull).
// =====================================================================
#define UQ_PITCH 160                       // floats per kq in U_s (8 groups x 20)
#define HBASE(b) ((b) * 512 + ((b) >> 2) * 8)
#define H_FLOATS (HBASE(31) + 512)         // 16440
#define REDPITCH 257                       // ull per slot-row
#define SMEM_FLOATS (128 * UQ_PITCH + H_FLOATS)
#define SMEM_BYTES  (SMEM_FLOATS * 4)

__global__ __launch_bounds__(256, 1) void lstm_rec_kernel(
    const float* __restrict__ U, float* __restrict__ out, size_t out_size)
{
    extern __shared__ float sm[];
    float* U_s = sm;                       // [128][160] skewed
    float* h_s = sm + 128 * UQ_PITCH;      // skewed rows; reused as red buffer

    const int t   = threadIdx.x;           // 0..255
    const int j   = blockIdx.x;            // 0..63
    const int bq  = blockIdx.y;            // 0..1  (barrier domain)

    // FMA-phase mapping
    const int q4 = t >> 6;                 // k quarter 0..3
    const int cg = t & 7;                  // col group: cols cg*4..+3
    const int bg = (t >> 3) & 7;           // batch group: b bg*4..+3

    // eltwise-phase mapping (fixed per thread across steps -> c_reg)
    const int hc = t & 7;
    const int b  = t >> 3;                 // 0..31
    const int col = j * 8 + hc;
    const int gb  = bq * 32 + b;

    unsigned long long* dom_flags = g_flags + (size_t)bq * 64 * 16;
    unsigned long long* red = (unsigned long long*)h_s;   // [16][257] overlay

    // ---- U slice load: col c of kq at (k>>2)*160 + (c>>2)*20 + (c&3)*4 + ki
    for (int idx = t; idx < 512 * 32; idx += 256) {
        int k = idx >> 5;
        int c = idx & 31;
        float v = U[(size_t)k * G_DIM + (c >> 3) * H_DIM + j * 8 + (c & 7)];
        U_s[(k >> 2) * UQ_PITCH + (c >> 2) * 20 + (c & 3) * 4 + (k & 3)] = v;
    }

    // ---- zero h_buf[0] (domain half: 64 CTAs x 256 floats = 32x512)
    {
        float* hz = g_h[0] + (size_t)bq * 32 * H_DIM;
        hz[j * 256 + t] = 0.0f;
    }

    unsigned long long base = ld_acquire_gpu(&dom_flags[j * 16]);

    // init barrier (domain-local)
    __syncthreads();
    if (t == 0) st_release_gpu(&dom_flags[j * 16], base + 1);
    if (t < 64) wait_flag_ge(&dom_flags[t * 16], base + 1);
    __syncthreads();

    float c_reg = 0.0f;

    for (int ts = 0; ts < S_LEN; ts++) {
        const int cur = ts & 1, nxt = cur ^ 1;

        // ---- xW prefetch for owned cell's 4 gates (hides DRAM latency)
        float xw[4];
        {
            const float* xb = g_xw + ((size_t)ts * B_DIM + gb) * G_DIM + j * 8 + hc;
            #pragma unroll
            for (int q = 0; q < 4; q++) xw[q] = __ldcs(xb + q * H_DIM);
        }

        // ---- wait for previous step's h (domain-local)
        if (ts > 0) {
            unsigned long long tgt = base + 1 + (unsigned long long)ts;
            if (t < 64) wait_flag_ge(&dom_flags[t * 16], tgt);
            __syncthreads();
        }

        // ---- h tile load: 32 rows x 512 floats; skewed row base,
        //      STS contiguous within row (0 conflicts), global coalesced.
        {
            const float* hb = g_h[cur] + (size_t)bq * 32 * H_DIM;
            #pragma unroll
            for (int n = 0; n < 16; n++) {
                int idx = n * 256 + t;         // 0..4095
                int row = idx >> 7;            // 0..31
                int c4  = idx & 127;           // float4 index in row
                float4 v = __ldcg((const float4*)(hb + row * H_DIM + c4 * 4));
                *(float4*)&h_s[HBASE(row) + c4 * 4] = v;
            }
        }
        __syncthreads();

        // ---- FMA: 4 cols x 4 batches x 32 kq per thread (k-quarter q4)
        unsigned long long acc[4][4];   // [ci][bi]
        #pragma unroll
        for (int ci = 0; ci < 4; ci++)
            #pragma unroll
            for (int bi = 0; bi < 4; bi++) acc[ci][bi] = 0ULL;

        const char* up = (const char*)(U_s + q4 * 32 * UQ_PITCH + cg * 20);
        const char* hp = (const char*)(h_s + HBASE(bg * 4)) + q4 * 512;
        #pragma unroll 4
        for (int kq = 0; kq < 32; kq++) {
            ulonglong2 u0 = *(const ulonglong2*)(up);
            ulonglong2 u1 = *(const ulonglong2*)(up + 16);
            ulonglong2 u2 = *(const ulonglong2*)(up + 32);
            ulonglong2 u3 = *(const ulonglong2*)(up + 48);
            ulonglong2 h0 = *(const ulonglong2*)(hp);
            ulonglong2 h1 = *(const ulonglong2*)(hp + 512 * 4);
            ulonglong2 h2 = *(const ulonglong2*)(hp + 1024 * 4);
            ulonglong2 h3 = *(const ulonglong2*)(hp + 1536 * 4);
            ffma2(acc[0][0], h0.x, u0.x); ffma2(acc[0][0], h0.y, u0.y);
            ffma2(acc[0][1], h1.x, u0.x); ffma2(acc[0][1], h1.y, u0.y);
            ffma2(acc[0][2], h2.x, u0.x); ffma2(acc[0][2], h2.y, u0.y);
            ffma2(acc[0][3], h3.x, u0.x); ffma2(acc[0][3], h3.y, u0.y);
            ffma2(acc[1][0], h0.x, u1.x); ffma2(acc[1][0], h0.y, u1.y);
            ffma2(acc[1][1], h1.x, u1.x); ffma2(acc[1][1], h1.y, u1.y);
            ffma2(acc[1][2], h2.x, u1.x); ffma2(acc[1][2], h2.y, u1.y);
            ffma2(acc[1][3], h3.x, u1.x); ffma2(acc[1][3], h3.y, u1.y);
            ffma2(acc[2][0], h0.x, u2.x); ffma2(acc[2][0], h0.y, u2.y);
            ffma2(acc[2][1], h1.x, u2.x); ffma2(acc[2][1], h1.y, u2.y);
            ffma2(acc[2][2], h2.x, u2.x); ffma2(acc[2][2], h2.y, u2.y);
            ffma2(acc[2][3], h3.x, u2.x); ffma2(acc[2][3], h3.y, u2.y);
            ffma2(acc[3][0], h0.x, u3.x); ffma2(acc[3][0], h0.y, u3.y);
            ffma2(acc[3][1], h1.x, u3.x); ffma2(acc[3][1], h1.y, u3.y);
            ffma2(acc[3][2], h2.x, u3.x); ffma2(acc[3][2], h2.y, u3.y);
            ffma2(acc[3][3], h3.x, u3.x); ffma2(acc[3][3], h3.y, u3.y);
            up += UQ_PITCH * 4;
            hp += 16;
        }

        // ---- all threads done reading h_s; reuse it as reduction buffer
        __syncthreads();
        {
            const int w = t;
            #pragma unroll
            for (int ci = 0; ci < 4; ci++)
                #pragma unroll
                for (int bi = 0; bi < 4; bi++)
                    red[(ci * 4 + bi) * REDPITCH + w] = acc[ci][bi];
        }
        __syncthreads();

        // ---- reduce 4 k-partials for owned cell (b, hc), all 4 gates
        float s[4];
        {
            const int slot = (hc & 3) * 4 + (b & 3);
            #pragma unroll
            for (int q = 0; q < 4; q++) {
                int c = q * 8 + hc;
                int tile = (b >> 2) * 8 + (c >> 2);
                unsigned long long v = red[slot * REDPITCH + tile];
                v = addf2(v, red[slot * REDPITCH +  64 + tile]);
                v = addf2(v, red[slot * REDPITCH + 128 + tile]);
                v = addf2(v, red[slot * REDPITCH + 192 + tile]);
                float l, h_;
                upk2(v, l, h_);
                s[q] = l + h_ + xw[q];
            }
        }

        float iv = sigmoid_f(s[0]);
        float fv = sigmoid_f(s[1]);
        float gv = tanh_f(s[2]);
        float ov = sigmoid_f(s[3]);

        c_reg = fv * c_reg + iv * gv;
        float hval = ov * tanh_f(c_reg);

        // ---- h store (critical), release, then out store (off-path)
        __stcg(&g_h[nxt][gb * H_DIM + col], hval);
        __syncthreads();
        if (ts < S_LEN - 1 && t == 0)
            st_release_gpu(&dom_flags[j * 16], base + 2 + (unsigned long long)ts);

        __stcs(&out[(size_t)ts * (B_DIM * H_DIM) + gb * H_DIM + col], hval);

        if (ts == S_LEN - 1) {
            const size_t SEQ  = (size_t)S_LEN * B_DIM * H_DIM;
            const size_t need = SEQ + 2 * (size_t)B_DIM * H_DIM;
            if (out_size >= need) {
                out[SEQ + gb * H_DIM + col]                         = hval;
                out[SEQ + (size_t)B_DIM * H_DIM + gb * H_DIM + col] = c_reg;
            }
        }
    }
}

// =====================================================================
extern "C" void kernel_launch(void* const* d_in, const int* in_sizes, int n_in,
                              void* d_out, int out_size) {
    const float* x    = (const float*)d_in[0];
    const float* W    = (const float*)d_in[1];
    const float* U    = (const float*)d_in[2];
    const float* bias = (const float*)d_in[3];
    float* out = (float*)d_out;
    (void)in_sizes; (void)n_in;

    cudaFuncSetAttribute(lstm_rec_kernel,
                         cudaFuncAttributeMaxDynamicSharedMemorySize, SMEM_BYTES);

    dim3 ggrid(G_DIM / 128, (S_LEN * B_DIM) / 128);  // (16, 1024)
    gemm_xw_kernel<<<ggrid, 256>>>(x, W, bias);

    dim3 rgrid(64, 2);  // 128 CTAs, 1/SM (smem-limited) -> all co-resident
    lstm_rec_kernel<<<rgrid, 256, SMEM_BYTES>>>(U, out, (size_t)out_size);
}